// round 2
// baseline (speedup 1.0000x reference)
#include <cuda_runtime.h>
#include <cstdint>
#include <math.h>

typedef unsigned long long ull;

#define B_    8
#define T_    1024
#define DL    1024
#define NH    8
#define DKH   128
#define DFF   2048
#define FH    256
#define MROWS (B_*T_)   /* 8192 */

// ---------------- scratch (device globals: allocation-free rule) ----------------
__device__ float g_H1[(size_t)MROWS*DFF];   // 64 MB
__device__ float g_X [(size_t)MROWS*DL];    // 32 MB
__device__ float g_Hn[(size_t)MROWS*DL];
__device__ float g_Q [(size_t)MROWS*DL];
__device__ float g_K [(size_t)MROWS*DL];
__device__ float g_V [(size_t)MROWS*DL];
__device__ float g_S [(size_t)B_*NH*T_*T_]; // 256 MB scores
__device__ float g_O [(size_t)MROWS*DL];
__device__ float g_F1[(size_t)MROWS*FH];

// ---------------- packed f32x2 helpers ----------------
__device__ __forceinline__ ull pack2(float x, float y){
    ull r; asm("mov.b64 %0, {%1,%2};" : "=l"(r) : "f"(x), "f"(y)); return r;
}
__device__ __forceinline__ void unpack2(ull v, float &x, float &y){
    asm("mov.b64 {%0,%1}, %2;" : "=f"(x), "=f"(y) : "l"(v));
}
__device__ __forceinline__ void ffma2(ull &c, ull a, ull b){
    asm("fma.rn.f32x2 %0, %1, %2, %0;" : "+l"(c) : "l"(a), "l"(b));
}

// ---------------- generic fp32 GEMM ----------------
// C[m,n] = alpha * sum_k A[m,k] * B'[k,n]  (+bias[n]) (relu) (+resid)
// NT=true : B is [N,K] row-major (B' = B^T), i.e. weights / K-major both sides
// NT=false: B is [K,N] row-major
// Batched via blockIdx.z with (z/batch2, z%batch2) offsets (b,h decomposition).
template<bool NT>
__global__ __launch_bounds__(256,2) void gemm_f32(
    const float* __restrict__ A, const float* __restrict__ Bm,
    float* __restrict__ C, const float* __restrict__ bias,
    const float* __restrict__ resid,
    int Kd, int lda, int ldb, int ldc,
    long long sA1, long long sA2, long long sB1, long long sB2,
    long long sC1, long long sC2,
    int batch2, float alpha, int relu)
{
    __shared__ float As[16][128];
    __shared__ float Bs[16][128];

    const int tid = threadIdx.x;
    const int z   = blockIdx.z;
    const int zb  = z / batch2;
    const int zh  = z - zb * batch2;

    const float* Ab = A + (size_t)zb*sA1 + (size_t)zh*sA2 + (size_t)blockIdx.y*128*lda;
    const float* Bb;
    if (NT) Bb = Bm + (size_t)zb*sB1 + (size_t)zh*sB2 + (size_t)blockIdx.x*128*ldb;
    else    Bb = Bm + (size_t)zb*sB1 + (size_t)zh*sB2 + (size_t)blockIdx.x*128;

    ull acc[8][4];
    #pragma unroll
    for (int i=0;i<8;i++)
        #pragma unroll
        for (int j=0;j<4;j++) acc[i][j] = 0ull;

    const int tr = (tid >> 4) << 3;   // 0..120, row in tile
    const int tc = (tid & 15) << 3;   // 0..120, col in tile

    for (int k0 = 0; k0 < Kd; k0 += 16) {
        #pragma unroll
        for (int i = 0; i < 2; i++) {
            int idx = tid*2 + i;                 // 0..511 float4 slots
            int r   = idx >> 2;                  // 0..127
            int c4  = (idx & 3) << 2;            // 0,4,8,12
            float4 v = *(const float4*)(Ab + (size_t)r*lda + k0 + c4);
            As[c4+0][r]=v.x; As[c4+1][r]=v.y; As[c4+2][r]=v.z; As[c4+3][r]=v.w;
            if (NT) {
                float4 w = *(const float4*)(Bb + (size_t)r*ldb + k0 + c4);
                Bs[c4+0][r]=w.x; Bs[c4+1][r]=w.y; Bs[c4+2][r]=w.z; Bs[c4+3][r]=w.w;
            } else {
                int rr = idx >> 5;               // 0..15
                int cc = (idx & 31) << 2;        // 0..124
                float4 w = *(const float4*)(Bb + (size_t)(k0+rr)*ldb + cc);
                *(float4*)&Bs[rr][cc] = w;
            }
        }
        __syncthreads();
        #pragma unroll
        for (int kk = 0; kk < 16; kk++) {
            float a[8];
            *(float4*)&a[0] = *(const float4*)&As[kk][tr];
            *(float4*)&a[4] = *(const float4*)&As[kk][tr+4];
            const float* bp = &Bs[kk][tc];
            ull b[4];
            b[0]=*(const ull*)(bp+0); b[1]=*(const ull*)(bp+2);
            b[2]=*(const ull*)(bp+4); b[3]=*(const ull*)(bp+6);
            #pragma unroll
            for (int i=0;i<8;i++){
                ull a2 = pack2(a[i], a[i]);
                #pragma unroll
                for (int j=0;j<4;j++) ffma2(acc[i][j], a2, b[j]);
            }
        }
        __syncthreads();
    }

    // ---- epilogue ----
    const size_t cbase = (size_t)zb*sC1 + (size_t)zh*sC2;
    const int row0 = blockIdx.y*128 + tr;
    const int col0 = blockIdx.x*128 + tc;
    float bv[8];
    #pragma unroll
    for (int j=0;j<8;j++) bv[j] = bias ? bias[col0+j] : 0.f;

    #pragma unroll
    for (int i=0;i<8;i++){
        float o[8];
        #pragma unroll
        for (int j=0;j<4;j++) unpack2(acc[i][j], o[2*j], o[2*j+1]);
        size_t roff = cbase + (size_t)(row0+i)*ldc + col0;
        #pragma unroll
        for (int j=0;j<8;j++){
            float v = o[j]*alpha + bv[j];
            if (relu) v = fmaxf(v, 0.f);
            o[j] = v;
        }
        if (resid) {
            float4 r0 = *(const float4*)(resid + roff);
            float4 r1 = *(const float4*)(resid + roff + 4);
            o[0]+=r0.x; o[1]+=r0.y; o[2]+=r0.z; o[3]+=r0.w;
            o[4]+=r1.x; o[5]+=r1.y; o[6]+=r1.z; o[7]+=r1.w;
        }
        float4 s0 = make_float4(o[0],o[1],o[2],o[3]);
        float4 s1 = make_float4(o[4],o[5],o[6],o[7]);
        *(float4*)(C + roff)     = s0;
        *(float4*)(C + roff + 4) = s1;
    }
}

// ---------------- LayerNorm: warp per row (D=1024, 32 floats/lane) ----------------
__global__ __launch_bounds__(128) void layernorm_k(
    const float* __restrict__ X, float* __restrict__ Y,
    const float* __restrict__ g, const float* __restrict__ b)
{
    const int row  = blockIdx.x*4 + (threadIdx.x >> 5);
    const int lane = threadIdx.x & 31;
    const float* p = X + (size_t)row*DL;

    float4 v[8];
    float s = 0.f;
    #pragma unroll
    for (int i=0;i<8;i++){
        v[i] = *(const float4*)(p + (i*32+lane)*4);
        s += v[i].x + v[i].y + v[i].z + v[i].w;
    }
    #pragma unroll
    for (int o=16;o>0;o>>=1) s += __shfl_xor_sync(0xffffffffu, s, o);
    const float m = s * (1.f/DL);

    float vs = 0.f;
    #pragma unroll
    for (int i=0;i<8;i++){
        float dx=v[i].x-m, dy=v[i].y-m, dz=v[i].z-m, dw=v[i].w-m;
        vs += dx*dx + dy*dy + dz*dz + dw*dw;
    }
    #pragma unroll
    for (int o=16;o>0;o>>=1) vs += __shfl_xor_sync(0xffffffffu, vs, o);
    const float r = rsqrtf(vs*(1.f/DL) + 1e-12f);

    float* q = Y + (size_t)row*DL;
    #pragma unroll
    for (int i=0;i<8;i++){
        int c = (i*32+lane)*4;
        float4 gg = *(const float4*)(g + c);
        float4 bb = *(const float4*)(b + c);
        float4 o;
        o.x = (v[i].x-m)*r*gg.x + bb.x;
        o.y = (v[i].y-m)*r*gg.y + bb.y;
        o.z = (v[i].z-m)*r*gg.z + bb.z;
        o.w = (v[i].w-m)*r*gg.w + bb.w;
        *(float4*)(q + c) = o;
    }
}

// ---------------- Softmax over rows of length 1024 (warp per row) ----------------
__global__ __launch_bounds__(128) void softmax_k(float* __restrict__ S)
{
    const int row  = blockIdx.x*4 + (threadIdx.x >> 5);
    const int lane = threadIdx.x & 31;
    float* p = S + (size_t)row*T_;

    float4 v[8];
    float mx = -INFINITY;
    #pragma unroll
    for (int i=0;i<8;i++){
        v[i] = *(const float4*)(p + (i*32+lane)*4);
        mx = fmaxf(mx, fmaxf(fmaxf(v[i].x,v[i].y), fmaxf(v[i].z,v[i].w)));
    }
    #pragma unroll
    for (int o=16;o>0;o>>=1) mx = fmaxf(mx, __shfl_xor_sync(0xffffffffu, mx, o));

    float s = 0.f;
    #pragma unroll
    for (int i=0;i<8;i++){
        v[i].x = __expf(v[i].x - mx);
        v[i].y = __expf(v[i].y - mx);
        v[i].z = __expf(v[i].z - mx);
        v[i].w = __expf(v[i].w - mx);
        s += v[i].x + v[i].y + v[i].z + v[i].w;
    }
    #pragma unroll
    for (int o=16;o>0;o>>=1) s += __shfl_xor_sync(0xffffffffu, s, o);
    const float inv = 1.f / s;

    #pragma unroll
    for (int i=0;i<8;i++){
        v[i].x*=inv; v[i].y*=inv; v[i].z*=inv; v[i].w*=inv;
        *(float4*)(p + (i*32+lane)*4) = v[i];
    }
}

// ---------------- host launch ----------------
static void launch_gemm(bool nt,
    const float*A, const float*B, float*C, const float*bias, const float*res,
    int M, int N, int Kd, int lda, int ldb, int ldc,
    long long sA1, long long sA2, long long sB1, long long sB2,
    long long sC1, long long sC2,
    int batch, int batch2, float alpha, int relu)
{
    dim3 grid(N/128, M/128, batch);
    dim3 blk(256);
    if (nt)
        gemm_f32<true ><<<grid,blk>>>(A,B,C,bias,res,Kd,lda,ldb,ldc,
                                      sA1,sA2,sB1,sB2,sC1,sC2,batch2,alpha,relu);
    else
        gemm_f32<false><<<grid,blk>>>(A,B,C,bias,res,Kd,lda,ldb,ldc,
                                      sA1,sA2,sB1,sB2,sC1,sC2,batch2,alpha,relu);
}

extern "C" void kernel_launch(void* const* d_in, const int* in_sizes, int n_in,
                              void* d_out, int out_size)
{
    (void)in_sizes; (void)n_in; (void)out_size;
    const float* x   = (const float*)d_in[0];
    const float* W1  = (const float*)d_in[1];
    const float* b1  = (const float*)d_in[2];
    const float* W2  = (const float*)d_in[3];
    const float* b2  = (const float*)d_in[4];
    const float* ln1g= (const float*)d_in[5];
    const float* ln1b= (const float*)d_in[6];
    const float* ln2g= (const float*)d_in[7];
    const float* ln2b= (const float*)d_in[8];
    const float* Wq  = (const float*)d_in[9];
    const float* bq  = (const float*)d_in[10];
    const float* Wk  = (const float*)d_in[11];
    const float* bk  = (const float*)d_in[12];
    const float* Wv  = (const float*)d_in[13];
    const float* bv  = (const float*)d_in[14];
    const float* Wo  = (const float*)d_in[15];
    const float* bo  = (const float*)d_in[16];
    const float* Fw1 = (const float*)d_in[17];
    const float* Fb1 = (const float*)d_in[18];
    const float* Fw2 = (const float*)d_in[19];
    const float* Fb2 = (const float*)d_in[20];
    float* out = (float*)d_out;

    float *H1,*X,*Hn,*Q,*Km,*V,*S,*O,*F1;
    cudaGetSymbolAddress((void**)&H1, g_H1);
    cudaGetSymbolAddress((void**)&X , g_X );
    cudaGetSymbolAddress((void**)&Hn, g_Hn);
    cudaGetSymbolAddress((void**)&Q , g_Q );
    cudaGetSymbolAddress((void**)&Km, g_K );
    cudaGetSymbolAddress((void**)&V , g_V );
    cudaGetSymbolAddress((void**)&S , g_S );
    cudaGetSymbolAddress((void**)&O , g_O );
    cudaGetSymbolAddress((void**)&F1, g_F1);

    const float scl = 0.08838834764831845f;  // DK^-0.5, DK=128

    // downsample: x[8192,1024] -> relu(xW1^T+b1)[8192,2048] -> W2^T+b2 -> X[8192,1024]
    launch_gemm(true, x,  W1, H1, b1, nullptr, MROWS, DFF, DL,  DL,  DL,  DFF,
                0,0,0,0,0,0, 1,1, 1.f, 1);
    launch_gemm(true, H1, W2, X,  b2, nullptr, MROWS, DL,  DFF, DFF, DFF, DL,
                0,0,0,0,0,0, 1,1, 1.f, 0);

    for (int l = 0; l < 2; l++) {
        const long long lw = (long long)l*DL*DL;
        // LN1
        layernorm_k<<<MROWS/4,128>>>(X, Hn, ln1g + l*DL, ln1b + l*DL);
        // QKV
        launch_gemm(true, Hn, Wq+lw, Q,  bq+l*DL, nullptr, MROWS, DL, DL, DL, DL, DL,
                    0,0,0,0,0,0, 1,1, 1.f, 0);
        launch_gemm(true, Hn, Wk+lw, Km, bk+l*DL, nullptr, MROWS, DL, DL, DL, DL, DL,
                    0,0,0,0,0,0, 1,1, 1.f, 0);
        launch_gemm(true, Hn, Wv+lw, V,  bv+l*DL, nullptr, MROWS, DL, DL, DL, DL, DL,
                    0,0,0,0,0,0, 1,1, 1.f, 0);
        // scores[b,h] = scl * Q_bh @ K_bh^T   (batched 64, z=(b*8+h))
        launch_gemm(true, Q, Km, S, nullptr, nullptr, T_, T_, DKH, DL, DL, T_,
                    (long long)T_*DL, DKH, (long long)T_*DL, DKH,
                    (long long)NH*T_*T_, (long long)T_*T_,
                    B_*NH, NH, scl, 0);
        softmax_k<<<(B_*NH*T_)/4,128>>>(S);
        // O[b,h] = attn @ V_bh   (NN)
        launch_gemm(false, S, V, O, nullptr, nullptr, T_, DKH, T_, T_, DL, DL,
                    (long long)NH*T_*T_, (long long)T_*T_,
                    (long long)T_*DL, DKH,
                    (long long)T_*DL, DKH,
                    B_*NH, NH, 1.f, 0);
        // X = X + O @ Wo^T + bo
        launch_gemm(true, O, Wo+lw, X, bo+l*DL, X, MROWS, DL, DL, DL, DL, DL,
                    0,0,0,0,0,0, 1,1, 1.f, 0);
        // LN2
        layernorm_k<<<MROWS/4,128>>>(X, Hn, ln2g + l*DL, ln2b + l*DL);
        // FFN
        launch_gemm(true, Hn, Fw1 + (long long)l*FH*DL, F1, Fb1 + l*FH, nullptr,
                    MROWS, FH, DL, DL, DL, FH, 0,0,0,0,0,0, 1,1, 1.f, 1);
        float* dst = (l == 1) ? out : X;
        launch_gemm(true, F1, Fw2 + (long long)l*DL*FH, dst, Fb2 + l*DL, X,
                    MROWS, DL, FH, FH, FH, DL, 0,0,0,0,0,0, 1,1, 1.f, 0);
    }
}

// round 5
// speedup vs baseline: 2.4071x; 2.4071x over previous
#include <cuda_runtime.h>
#include <cuda_bf16.h>
#include <cstdint>
#include <math.h>
typedef long long ll;
typedef __nv_bfloat16 bf;
typedef __nv_bfloat162 bf2;

#define B_ 8
#define T_ 1024
#define DL 1024
#define NH 8
#define DKH 128
#define DFF 2048
#define FH 256
#define MROWS 8192

// ---------------- device scratch ----------------
__device__ __align__(128) bf    g_x3 [(size_t)MROWS*3*DL];
__device__ __align__(128) bf    g_W13[(size_t)DFF*3*DL];
__device__ __align__(128) bf    g_H13[(size_t)MROWS*3*DFF];
__device__ __align__(128) bf    g_W23[(size_t)DL*3*DFF];
__device__ __align__(128) float g_X  [(size_t)MROWS*DL];
__device__ __align__(128) bf    g_Hn3[(size_t)MROWS*3*DL];
__device__ __align__(128) bf    g_Wq3[(size_t)DL*3*DL];
__device__ __align__(128) bf    g_Wk3[(size_t)DL*3*DL];
__device__ __align__(128) bf    g_Wv3[(size_t)DL*3*DL];
__device__ __align__(128) bf    g_Wo3[(size_t)DL*3*DL];
__device__ __align__(128) bf    g_Fw13[(size_t)FH*3*DL];
__device__ __align__(128) bf    g_Fw23[(size_t)DL*3*FH];
__device__ __align__(128) bf    g_Q3 [(size_t)MROWS*3*DL];   // FIXED: (b,h,t) x 3*DKH = 64*1024*384
__device__ __align__(128) bf    g_K3 [(size_t)MROWS*3*DL];   // FIXED: same
__device__ __align__(128) float g_V  [(size_t)MROWS*DL];
__device__ __align__(128) bf    g_Vt3[(size_t)B_*NH*DKH*3*T_];
__device__ __align__(128) float g_S  [(size_t)B_*NH*T_*T_];
__device__ __align__(128) bf    g_S3 [(size_t)B_*NH*T_*3*T_];
__device__ __align__(128) bf    g_O3 [(size_t)MROWS*3*DL];
__device__ __align__(128) bf    g_F13[(size_t)MROWS*3*FH];

// ---------------- helpers ----------------
__device__ __forceinline__ uint32_t smem_u32(const void* p){
    uint32_t a;
    asm("{ .reg .u64 t; cvta.to.shared.u64 t, %1; cvt.u32.u64 %0, t; }" : "=r"(a) : "l"(p));
    return a;
}
__device__ __forceinline__ void cp16(uint32_t s, const void* g){
    asm volatile("cp.async.cg.shared.global [%0], [%1], 16;" :: "r"(s), "l"(g));
}
#define CP_COMMIT() asm volatile("cp.async.commit_group;")
#define CP_WAIT0()  asm volatile("cp.async.wait_group 0;" ::: "memory")
#define CP_WAIT1()  asm volatile("cp.async.wait_group 1;" ::: "memory")
#define SWZ(o) ((o) ^ (((o)>>3)&0x70))

__device__ __forceinline__ void ldsm4(uint32_t &r0, uint32_t &r1, uint32_t &r2, uint32_t &r3, uint32_t a){
    asm volatile("ldmatrix.sync.aligned.m8n8.x4.shared.b16 {%0,%1,%2,%3}, [%4];"
                 : "=r"(r0), "=r"(r1), "=r"(r2), "=r"(r3) : "r"(a));
}
__device__ __forceinline__ void mma16816(float* d, const uint32_t* a, uint32_t b0, uint32_t b1){
    asm volatile("mma.sync.aligned.m16n8k16.row.col.f32.bf16.bf16.f32 "
                 "{%0,%1,%2,%3}, {%4,%5,%6,%7}, {%8,%9}, {%0,%1,%2,%3};"
                 : "+f"(d[0]), "+f"(d[1]), "+f"(d[2]), "+f"(d[3])
                 : "r"(a[0]), "r"(a[1]), "r"(a[2]), "r"(a[3]), "r"(b0), "r"(b1));
}
__device__ __forceinline__ void trip(float x, bf &h, bf &l){
    h = __float2bfloat16(x);
    l = __float2bfloat16(x - __bfloat162float(h));
}

// ================= mma.sync GEMM: C = alpha*A(K-major)@B(K-major)^T (+bias)(relu)(+resid) ====
// CTA 128x128, K-chunk 64, 8 warps (2m x 4n), warp tile 64x32.
// modes: 0=fp32 out(+resid), 1=triple-A (ldc3,toff), 2=Q head triple-A, 3=K head triple-B, 4=O head triple-A
__global__ __launch_bounds__(256,2) void gemm_m(
    const bf* __restrict__ A, const bf* __restrict__ Bm,
    int Kp, int lda, int ldb,
    ll sA1, ll sA2, ll sB1, ll sB2, int batch2,
    int mode, int relu, float alpha,
    const float* __restrict__ bias, const float* __restrict__ resid,
    float* __restrict__ Cf, ll sC1, ll sC2, int ldc,
    bf* __restrict__ C3, int toff, int ldc3)
{
    constexpr int STAGE = 32768;            // 16KB A + 16KB B
    extern __shared__ char dyn[];
    const uint32_t sbase = (smem_u32(dyn) + 1023) & ~1023u;

    const int tid  = threadIdx.x;
    const int lane = tid & 31;
    const int wid  = tid >> 5;
    const int wm   = (wid >> 2) * 64;       // warp m offset in tile
    const int wn   = (wid & 3) * 32;        // warp n offset in tile

    const int z  = blockIdx.z;
    const int zb = z / batch2, zh = z - zb*batch2;
    const bf* Ab = A  + zb*sA1 + zh*sA2 + (ll)blockIdx.y*128*lda;
    const bf* Bb = Bm + zb*sB1 + zh*sB2 + (ll)blockIdx.x*128*ldb;

    float acc[4][4][4];
    #pragma unroll
    for (int i=0;i<4;i++)
        #pragma unroll
        for (int j=0;j<4;j++)
            #pragma unroll
            for (int r=0;r<4;r++) acc[i][j][r] = 0.f;

    const int nchunk = Kp >> 6;

    // ---- loader ----
    #define LOAD_CHUNK(c, s) do { \
        const int k0_ = (c) << 6; \
        const uint32_t sa_ = sbase + (s)*STAGE; \
        const uint32_t sb_ = sa_ + 16384; \
        _Pragma("unroll") \
        for (int i_ = 0; i_ < 4; i_++){ \
            int idx_ = tid + i_*256; \
            int r_ = idx_>>3, j_ = idx_&7; \
            cp16(sa_ + SWZ(r_*128 + j_*16), Ab + (ll)r_*lda + k0_ + j_*8); \
        } \
        _Pragma("unroll") \
        for (int i_ = 0; i_ < 4; i_++){ \
            int idx_ = tid + i_*256; \
            int r_ = idx_>>3, j_ = idx_&7; \
            cp16(sb_ + SWZ(r_*128 + j_*16), Bb + (ll)r_*ldb + k0_ + j_*8); \
        } \
        CP_COMMIT(); \
    } while(0)

    LOAD_CHUNK(0, 0);
    if (nchunk > 1) LOAD_CHUNK(1, 1);

    const int la = lane & 15;      // row within 16-row ldmatrix block
    const int lh = lane >> 4;      // k-half selector

    for (int c = 0; c < nchunk; c++){
        if (c + 1 < nchunk) { CP_WAIT1(); } else { CP_WAIT0(); }
        __syncthreads();
        const int s = c & 1;
        const uint32_t sa = sbase + s*STAGE;
        const uint32_t sb = sa + 16384;

        #pragma unroll
        for (int kk = 0; kk < 4; kk++){
            const int colb = kk*32 + lh*16;            // byte offset of k within row
            uint32_t af[4][4];
            #pragma unroll
            for (int i = 0; i < 4; i++){
                uint32_t o = (uint32_t)((wm + i*16 + la)*128 + colb);
                ldsm4(af[i][0], af[i][1], af[i][2], af[i][3], sa + SWZ(o));
            }
            uint32_t bfr[2][4];
            #pragma unroll
            for (int j = 0; j < 2; j++){
                uint32_t o = (uint32_t)((wn + j*16 + la)*128 + colb);
                ldsm4(bfr[j][0], bfr[j][1], bfr[j][2], bfr[j][3], sb + SWZ(o));
            }
            #pragma unroll
            for (int i = 0; i < 4; i++)
                #pragma unroll
                for (int jn = 0; jn < 4; jn++){
                    uint32_t b0 = (jn&1) ? bfr[jn>>1][1] : bfr[jn>>1][0];
                    uint32_t b1 = (jn&1) ? bfr[jn>>1][3] : bfr[jn>>1][2];
                    mma16816(acc[i][jn], af[i], b0, b1);
                }
        }
        __syncthreads();
        if (c + 2 < nchunk) LOAD_CHUNK(c + 2, s);
    }
    #undef LOAD_CHUNK

    // ---------------- epilogue (registers -> gmem) ----------------
    const int g  = lane >> 2;
    const int tg = (lane & 3) * 2;

    auto store2 = [&](int row, int cg, float v0, float v1){
        v0 = v0*alpha; v1 = v1*alpha;
        if (bias){ v0 += __ldg(bias+cg); v1 += __ldg(bias+cg+1); }
        if (relu){ v0 = fmaxf(v0,0.f); v1 = fmaxf(v1,0.f); }
        if (mode == 0){
            const ll base = zb*sC1 + zh*sC2 + (ll)row*ldc + cg;
            float2 w = make_float2(v0, v1);
            if (resid){
                float2 rr = *(const float2*)(resid + base);
                w.x += rr.x; w.y += rr.y;
            }
            *(float2*)(Cf + base) = w;
        } else {
            bf h0,l0,h1,l1; trip(v0,h0,l0); trip(v1,h1,l1);
            bf2 hh; hh.x=h0; hh.y=h1;
            bf2 lo; lo.x=l0; lo.y=l1;
            if (mode == 1){
                const ll base = (ll)row*ldc3 + cg;
                *(bf2*)(C3+base)        = hh;
                *(bf2*)(C3+base+toff)   = lo;
                *(bf2*)(C3+base+2*toff) = hh;
            } else if (mode == 2 || mode == 3){
                const int b = row>>10, t = row&1023, h = cg>>7, d0 = cg&127;
                const ll base = ((ll)(b*8+h)*1024 + t)*384 + d0;
                *(bf2*)(C3+base) = hh;
                if (mode==2){ *(bf2*)(C3+base+128) = lo; *(bf2*)(C3+base+256) = hh; }
                else        { *(bf2*)(C3+base+128) = hh; *(bf2*)(C3+base+256) = lo; }
            } else { // mode 4
                const ll base = ((ll)zb*1024 + row)*3072 + zh*128 + cg;
                *(bf2*)(C3+base)      = hh;
                *(bf2*)(C3+base+1024) = lo;
                *(bf2*)(C3+base+2048) = hh;
            }
        }
    };

    #pragma unroll
    for (int i = 0; i < 4; i++){
        const int r0 = blockIdx.y*128 + wm + i*16 + g;
        #pragma unroll
        for (int jn = 0; jn < 4; jn++){
            const int cg = blockIdx.x*128 + wn + jn*8 + tg;
            store2(r0,     cg, acc[i][jn][0], acc[i][jn][1]);
            store2(r0 + 8, cg, acc[i][jn][2], acc[i][jn][3]);
        }
    }
}

// ---------------- fp32 -> bf16 triple ----------------
__global__ void conv_k(const float* __restrict__ in, bf* __restrict__ out,
                       int Kd, int isB, int n)
{
    int i = blockIdx.x*256 + threadIdx.x;
    if (i >= n) return;
    int r = i / Kd, c = i - r*Kd;
    bf h, l; trip(in[i], h, l);
    ll base = (ll)r*3*Kd + c;
    if (isB){ out[base]=h; out[base+Kd]=h; out[base+2*Kd]=l; }
    else    { out[base]=h; out[base+Kd]=l; out[base+2*Kd]=h; }
}

// ---------------- LayerNorm -> triple-A, ld 3072 ----------------
__global__ __launch_bounds__(128) void layernorm_k(
    const float* __restrict__ X, bf* __restrict__ Y3,
    const float* __restrict__ g, const float* __restrict__ b)
{
    const int row  = blockIdx.x*4 + (threadIdx.x >> 5);
    const int lane = threadIdx.x & 31;
    const float* p = X + (ll)row*DL;
    float4 v[8]; float s = 0.f;
    #pragma unroll
    for (int i=0;i<8;i++){
        v[i] = *(const float4*)(p + (i*32+lane)*4);
        s += v[i].x + v[i].y + v[i].z + v[i].w;
    }
    #pragma unroll
    for (int o=16;o>0;o>>=1) s += __shfl_xor_sync(0xffffffffu, s, o);
    const float m = s * (1.f/DL);
    float vs = 0.f;
    #pragma unroll
    for (int i=0;i<8;i++){
        float dx=v[i].x-m, dy=v[i].y-m, dz=v[i].z-m, dw=v[i].w-m;
        vs += dx*dx + dy*dy + dz*dz + dw*dw;
    }
    #pragma unroll
    for (int o=16;o>0;o>>=1) vs += __shfl_xor_sync(0xffffffffu, vs, o);
    const float r = rsqrtf(vs*(1.f/DL) + 1e-12f);
    bf* q = Y3 + (ll)row*3072;
    #pragma unroll
    for (int i=0;i<8;i++){
        int c = (i*32+lane)*4;
        float4 gg = *(const float4*)(g + c);
        float4 bb = *(const float4*)(b + c);
        float o0=(v[i].x-m)*r*gg.x+bb.x, o1=(v[i].y-m)*r*gg.y+bb.y;
        float o2=(v[i].z-m)*r*gg.z+bb.z, o3=(v[i].w-m)*r*gg.w+bb.w;
        bf h0,l0,h1,l1,h2,l2,h3,l3;
        trip(o0,h0,l0); trip(o1,h1,l1); trip(o2,h2,l2); trip(o3,h3,l3);
        bf2 a,bp; a.x=h0;a.y=h1; bp.x=h2;bp.y=h3;
        *(bf2*)(q+c)=a;        *(bf2*)(q+c+2)=bp;
        bf2 la,lb; la.x=l0;la.y=l1; lb.x=l2;lb.y=l3;
        *(bf2*)(q+1024+c)=la;  *(bf2*)(q+1024+c+2)=lb;
        *(bf2*)(q+2048+c)=a;   *(bf2*)(q+2048+c+2)=bp;
    }
}

// ---------------- softmax rows of 1024 -> triple-A, ld 3072 ----------------
__global__ __launch_bounds__(128) void softmax_k(
    const float* __restrict__ S, bf* __restrict__ S3)
{
    const int row  = blockIdx.x*4 + (threadIdx.x >> 5);
    const int lane = threadIdx.x & 31;
    const float* p = S + (ll)row*T_;
    float4 v[8]; float mx = -INFINITY;
    #pragma unroll
    for (int i=0;i<8;i++){
        v[i] = *(const float4*)(p + (i*32+lane)*4);
        mx = fmaxf(mx, fmaxf(fmaxf(v[i].x,v[i].y), fmaxf(v[i].z,v[i].w)));
    }
    #pragma unroll
    for (int o=16;o>0;o>>=1) mx = fmaxf(mx, __shfl_xor_sync(0xffffffffu, mx, o));
    float s = 0.f;
    #pragma unroll
    for (int i=0;i<8;i++){
        v[i].x=__expf(v[i].x-mx); v[i].y=__expf(v[i].y-mx);
        v[i].z=__expf(v[i].z-mx); v[i].w=__expf(v[i].w-mx);
        s += v[i].x + v[i].y + v[i].z + v[i].w;
    }
    #pragma unroll
    for (int o=16;o>0;o>>=1) s += __shfl_xor_sync(0xffffffffu, s, o);
    const float inv = 1.f / s;
    bf* q = S3 + (ll)row*3072;
    #pragma unroll
    for (int i=0;i<8;i++){
        int c = (i*32+lane)*4;
        float o0=v[i].x*inv, o1=v[i].y*inv, o2=v[i].z*inv, o3=v[i].w*inv;
        bf h0,l0,h1,l1,h2,l2,h3,l3;
        trip(o0,h0,l0); trip(o1,h1,l1); trip(o2,h2,l2); trip(o3,h3,l3);
        bf2 a,bp; a.x=h0;a.y=h1; bp.x=h2;bp.y=h3;
        *(bf2*)(q+c)=a;        *(bf2*)(q+c+2)=bp;
        bf2 la,lb; la.x=l0;la.y=l1; lb.x=l2;lb.y=l3;
        *(bf2*)(q+1024+c)=la;  *(bf2*)(q+1024+c+2)=lb;
        *(bf2*)(q+2048+c)=a;   *(bf2*)(q+2048+c+2)=bp;
    }
}

// ---------------- V transpose -> per-head [d, 3*T] triple-B ----------------
__global__ void vt_k(const float* __restrict__ V, bf* __restrict__ Vt3)
{
    __shared__ float t[32][33];
    const int bh = blockIdx.z, d0 = blockIdx.x*32, t0 = blockIdx.y*32;
    const int b = bh>>3, h = bh&7;
    const int tx = threadIdx.x, ty = threadIdx.y;
    t[ty][tx] = V[((ll)b*T_ + t0+ty)*DL + h*DKH + d0+tx];
    __syncthreads();
    float x = t[tx][ty];
    bf hh, lo; trip(x, hh, lo);
    const ll base = ((ll)bh*DKH + d0+ty)*(3*T_) + t0+tx;
    Vt3[base]       = hh;
    Vt3[base+T_]    = hh;
    Vt3[base+2*T_]  = lo;
}

// ---------------- host ----------------
static void gm(const bf*A,const bf*B,int M,int N,int Kp,int lda,int ldb,
    ll sA1,ll sA2,ll sB1,ll sB2,int batch,int batch2,int mode,int relu,float alpha,
    const float*bias,const float*resid,float*Cf,ll sC1,ll sC2,int ldc,bf*C3,int toff,int ldc3)
{
    dim3 g(N/128, M/128, batch);
    gemm_m<<<g,256,66560>>>(A,B,Kp,lda,ldb,sA1,sA2,sB1,sB2,batch2,
        mode,relu,alpha,bias,resid,Cf,sC1,sC2,ldc,C3,toff,ldc3);
}
static void conv(const float* in, bf* out, int Kd, int isB, int n){
    conv_k<<<(n+255)/256,256>>>(in, out, Kd, isB, n);
}

extern "C" void kernel_launch(void* const* d_in, const int* in_sizes, int n_in,
                              void* d_out, int out_size)
{
    (void)in_sizes; (void)n_in; (void)out_size;
    const float* x   = (const float*)d_in[0];
    const float* W1  = (const float*)d_in[1];
    const float* b1  = (const float*)d_in[2];
    const float* W2  = (const float*)d_in[3];
    const float* b2  = (const float*)d_in[4];
    const float* ln1g= (const float*)d_in[5];
    const float* ln1b= (const float*)d_in[6];
    const float* ln2g= (const float*)d_in[7];
    const float* ln2b= (const float*)d_in[8];
    const float* Wq  = (const float*)d_in[9];
    const float* bq  = (const float*)d_in[10];
    const float* Wk  = (const float*)d_in[11];
    const float* bk  = (const float*)d_in[12];
    const float* Wv  = (const float*)d_in[13];
    const float* bv  = (const float*)d_in[14];
    const float* Wo  = (const float*)d_in[15];
    const float* bo  = (const float*)d_in[16];
    const float* Fw1 = (const float*)d_in[17];
    const float* Fb1 = (const float*)d_in[18];
    const float* Fw2 = (const float*)d_in[19];
    const float* Fb2 = (const float*)d_in[20];
    float* out = (float*)d_out;

    cudaFuncSetAttribute(gemm_m, cudaFuncAttributeMaxDynamicSharedMemorySize, 66560);

    bf *x3,*W13,*H13,*W23,*Hn3,*Wq3,*Wk3,*Wv3,*Wo3,*Fw13,*Fw23,*Q3,*K3,*Vt3,*S3,*O3,*F13;
    float *X,*V,*S;
    cudaGetSymbolAddress((void**)&x3 , g_x3 );
    cudaGetSymbolAddress((void**)&W13, g_W13);
    cudaGetSymbolAddress((void**)&H13, g_H13);
    cudaGetSymbolAddress((void**)&W23, g_W23);
    cudaGetSymbolAddress((void**)&X  , g_X  );
    cudaGetSymbolAddress((void**)&Hn3, g_Hn3);
    cudaGetSymbolAddress((void**)&Wq3, g_Wq3);
    cudaGetSymbolAddress((void**)&Wk3, g_Wk3);
    cudaGetSymbolAddress((void**)&Wv3, g_Wv3);
    cudaGetSymbolAddress((void**)&Wo3, g_Wo3);
    cudaGetSymbolAddress((void**)&Fw13, g_Fw13);
    cudaGetSymbolAddress((void**)&Fw23, g_Fw23);
    cudaGetSymbolAddress((void**)&Q3 , g_Q3 );
    cudaGetSymbolAddress((void**)&K3 , g_K3 );
    cudaGetSymbolAddress((void**)&V  , g_V  );
    cudaGetSymbolAddress((void**)&Vt3, g_Vt3);
    cudaGetSymbolAddress((void**)&S  , g_S  );
    cudaGetSymbolAddress((void**)&S3 , g_S3 );
    cudaGetSymbolAddress((void**)&O3 , g_O3 );
    cudaGetSymbolAddress((void**)&F13, g_F13);

    const float scl = 0.08838834764831845f; // 128^-0.5

    // ---- downsample ----
    conv(x,  x3,  DL,  0, MROWS*DL);
    conv(W1, W13, DL,  1, DFF*DL);
    conv(W2, W23, DFF, 1, DL*DFF);
    gm(x3, W13, MROWS, DFF, 3*DL, 3*DL, 3*DL, 0,0,0,0, 1,1,
       1,1,1.f, b1, nullptr, nullptr,0,0,0, H13, DFF, 3*DFF);
    gm(H13, W23, MROWS, DL, 3*DFF, 3*DFF, 3*DFF, 0,0,0,0, 1,1,
       0,0,1.f, b2, nullptr, X, 0,0,DL, nullptr,0,0);

    for (int l = 0; l < 2; l++){
        const ll lw = (ll)l*DL*DL;
        conv(Wq+lw, Wq3, DL, 1, DL*DL);
        conv(Wk+lw, Wk3, DL, 1, DL*DL);
        conv(Wv+lw, Wv3, DL, 1, DL*DL);
        conv(Wo+lw, Wo3, DL, 1, DL*DL);
        conv(Fw1+(ll)l*FH*DL, Fw13, DL, 1, FH*DL);
        conv(Fw2+(ll)l*DL*FH, Fw23, FH, 1, DL*FH);

        layernorm_k<<<MROWS/4,128>>>(X, Hn3, ln1g+l*DL, ln1b+l*DL);
        gm(Hn3, Wq3, MROWS, DL, 3*DL, 3*DL, 3*DL, 0,0,0,0, 1,1,
           2,0,1.f, bq+l*DL, nullptr, nullptr,0,0,0, Q3, 0,0);
        gm(Hn3, Wk3, MROWS, DL, 3*DL, 3*DL, 3*DL, 0,0,0,0, 1,1,
           3,0,1.f, bk+l*DL, nullptr, nullptr,0,0,0, K3, 0,0);
        gm(Hn3, Wv3, MROWS, DL, 3*DL, 3*DL, 3*DL, 0,0,0,0, 1,1,
           0,0,1.f, bv+l*DL, nullptr, V, 0,0,DL, nullptr,0,0);
        vt_k<<<dim3(DKH/32, T_/32, B_*NH), dim3(32,32)>>>(V, Vt3);

        // scores = scl * Q @ K^T   [64 batched]
        gm(Q3, K3, T_, T_, 3*DKH, 3*DKH, 3*DKH,
           (ll)NH*T_*3*DKH, (ll)T_*3*DKH, (ll)NH*T_*3*DKH, (ll)T_*3*DKH,
           B_*NH, NH, 0,0,scl, nullptr, nullptr,
           S, (ll)NH*T_*T_, (ll)T_*T_, T_, nullptr,0,0);
        softmax_k<<<(B_*NH*T_)/4,128>>>(S, S3);
        // O = attn @ V   [64 batched]
        gm(S3, Vt3, T_, DKH, 3*T_, 3*T_, 3*T_,
           (ll)NH*T_*3*T_, (ll)T_*3*T_, (ll)NH*DKH*3*T_, (ll)DKH*3*T_,
           B_*NH, NH, 4,0,1.f, nullptr, nullptr,
           nullptr,0,0,0, O3, 0,0);
        // X = X + O @ Wo^T + bo
        gm(O3, Wo3, MROWS, DL, 3*DL, 3*DL, 3*DL, 0,0,0,0, 1,1,
           0,0,1.f, bo+l*DL, X, X, 0,0,DL, nullptr,0,0);

        layernorm_k<<<MROWS/4,128>>>(X, Hn3, ln2g+l*DL, ln2b+l*DL);
        gm(Hn3, Fw13, MROWS, FH, 3*DL, 3*DL, 3*DL, 0,0,0,0, 1,1,
           1,1,1.f, Fb1+l*FH, nullptr, nullptr,0,0,0, F13, FH, 3*FH);
        float* dst = (l==1) ? out : X;
        gm(F13, Fw23, MROWS, DL, 3*FH, 3*FH, 3*FH, 0,0,0,0, 1,1,
           0,0,1.f, Fb2+l*DL, X, dst, 0,0,DL, nullptr,0,0);
    }
}

// round 6
// speedup vs baseline: 3.3996x; 1.4123x over previous
#include <cuda_runtime.h>
#include <cuda_fp16.h>
#include <cstdint>
#include <math.h>
typedef long long ll;
typedef __half hf;
typedef __half2 hf2;

#define B_ 8
#define T_ 1024
#define DL 1024
#define NH 8
#define DKH 128
#define DFF 2048
#define FH 256
#define MROWS 8192

// ---------------- device scratch ----------------
__device__ __align__(128) hf    g_x2 [(size_t)MROWS*2*DL];
__device__ __align__(128) hf    g_W12[(size_t)DFF*2*DL];
__device__ __align__(128) hf    g_H12[(size_t)MROWS*2*DFF];
__device__ __align__(128) hf    g_W22[(size_t)DL*2*DFF];
__device__ __align__(128) float g_X  [(size_t)MROWS*DL];
__device__ __align__(128) hf    g_Hn2[(size_t)MROWS*2*DL];
__device__ __align__(128) hf    g_Wq2[(size_t)DL*2*DL];
__device__ __align__(128) hf    g_Wk2[(size_t)DL*2*DL];
__device__ __align__(128) hf    g_Wv2[(size_t)DL*2*DL];
__device__ __align__(128) hf    g_Wo2[(size_t)DL*2*DL];
__device__ __align__(128) hf    g_Fw12[(size_t)FH*2*DL];
__device__ __align__(128) hf    g_Fw22[(size_t)DL*2*FH];
__device__ __align__(128) hf    g_Q2 [(size_t)MROWS*2*DL];   // (b,h,t) x 2*DKH = 64*1024*256
__device__ __align__(128) hf    g_K2 [(size_t)MROWS*2*DL];
__device__ __align__(128) float g_V  [(size_t)MROWS*DL];
__device__ __align__(128) hf    g_Vt2[(size_t)B_*NH*DKH*2*T_];
__device__ __align__(128) float g_S  [(size_t)B_*NH*T_*T_];
__device__ __align__(128) hf    g_S2 [(size_t)B_*NH*T_*2*T_];
__device__ __align__(128) hf    g_O2 [(size_t)MROWS*2*DL];
__device__ __align__(128) hf    g_F12[(size_t)MROWS*2*FH];

// ---------------- helpers ----------------
__device__ __forceinline__ uint32_t smem_u32(const void* p){
    uint32_t a;
    asm("{ .reg .u64 t; cvta.to.shared.u64 t, %1; cvt.u32.u64 %0, t; }" : "=r"(a) : "l"(p));
    return a;
}
__device__ __forceinline__ void cp16(uint32_t s, const void* g){
    asm volatile("cp.async.cg.shared.global [%0], [%1], 16;" :: "r"(s), "l"(g));
}
#define CP_COMMIT() asm volatile("cp.async.commit_group;")
#define CP_WAIT0()  asm volatile("cp.async.wait_group 0;" ::: "memory")
#define CP_WAIT1()  asm volatile("cp.async.wait_group 1;" ::: "memory")
#define SWZ(o) ((o) ^ (((o)>>3)&0x70))

__device__ __forceinline__ void ldsm4(uint32_t &r0, uint32_t &r1, uint32_t &r2, uint32_t &r3, uint32_t a){
    asm volatile("ldmatrix.sync.aligned.m8n8.x4.shared.b16 {%0,%1,%2,%3}, [%4];"
                 : "=r"(r0), "=r"(r1), "=r"(r2), "=r"(r3) : "r"(a));
}
__device__ __forceinline__ void mma16816(float* d, const uint32_t* a, uint32_t b0, uint32_t b1){
    asm volatile("mma.sync.aligned.m16n8k16.row.col.f32.f16.f16.f32 "
                 "{%0,%1,%2,%3}, {%4,%5,%6,%7}, {%8,%9}, {%0,%1,%2,%3};"
                 : "+f"(d[0]), "+f"(d[1]), "+f"(d[2]), "+f"(d[3])
                 : "r"(a[0]), "r"(a[1]), "r"(a[2]), "r"(a[3]), "r"(b0), "r"(b1));
}
__device__ __forceinline__ void trip(float x, hf &h, hf &l){
    h = __float2half_rn(x);
    l = __float2half_rn(x - __half2float(h));
}

// ================= mma.sync GEMM: C = alpha*A(K-major)@B(K-major)^T (+bias)(relu)(+resid) ====
// CTA 128x128, K-chunk 64, 8 warps (2m x 4n), warp tile 64x32.
// modes: 0=fp32 out(+resid), 1=pair-A (ldc3,toff), 2=Q head pair-A, 3=K head pair-B, 4=O head pair-A
__global__ __launch_bounds__(256,2) void gemm_m(
    const hf* __restrict__ A, const hf* __restrict__ Bm,
    int Kp, int lda, int ldb,
    ll sA1, ll sA2, ll sB1, ll sB2, int batch2,
    int mode, int relu, float alpha,
    const float* __restrict__ bias, const float* __restrict__ resid,
    float* __restrict__ Cf, ll sC1, ll sC2, int ldc,
    hf* __restrict__ C2, int toff, int ldc3)
{
    constexpr int STAGE = 32768;            // 16KB A + 16KB B
    extern __shared__ char dyn[];
    const uint32_t sbase = (smem_u32(dyn) + 1023) & ~1023u;

    const int tid  = threadIdx.x;
    const int lane = tid & 31;
    const int wid  = tid >> 5;
    const int wm   = (wid >> 2) * 64;       // warp m offset in tile
    const int wn   = (wid & 3) * 32;        // warp n offset in tile

    const int z  = blockIdx.z;
    const int zb = z / batch2, zh = z - zb*batch2;
    const hf* Ab = A  + zb*sA1 + zh*sA2 + (ll)blockIdx.y*128*lda;
    const hf* Bb = Bm + zb*sB1 + zh*sB2 + (ll)blockIdx.x*128*ldb;

    float acc[4][4][4];
    #pragma unroll
    for (int i=0;i<4;i++)
        #pragma unroll
        for (int j=0;j<4;j++)
            #pragma unroll
            for (int r=0;r<4;r++) acc[i][j][r] = 0.f;

    const int nchunk = Kp >> 6;

    // ---- loader ----
    #define LOAD_CHUNK(c, s) do { \
        const int k0_ = (c) << 6; \
        const uint32_t sa_ = sbase + (s)*STAGE; \
        const uint32_t sb_ = sa_ + 16384; \
        _Pragma("unroll") \
        for (int i_ = 0; i_ < 4; i_++){ \
            int idx_ = tid + i_*256; \
            int r_ = idx_>>3, j_ = idx_&7; \
            cp16(sa_ + SWZ(r_*128 + j_*16), Ab + (ll)r_*lda + k0_ + j_*8); \
        } \
        _Pragma("unroll") \
        for (int i_ = 0; i_ < 4; i_++){ \
            int idx_ = tid + i_*256; \
            int r_ = idx_>>3, j_ = idx_&7; \
            cp16(sb_ + SWZ(r_*128 + j_*16), Bb + (ll)r_*ldb + k0_ + j_*8); \
        } \
        CP_COMMIT(); \
    } while(0)

    LOAD_CHUNK(0, 0);
    if (nchunk > 1) LOAD_CHUNK(1, 1);

    const int la = lane & 15;      // row within 16-row ldmatrix block
    const int lh = lane >> 4;      // k-half selector

    for (int c = 0; c < nchunk; c++){
        if (c + 1 < nchunk) { CP_WAIT1(); } else { CP_WAIT0(); }
        __syncthreads();
        const int s = c & 1;
        const uint32_t sa = sbase + s*STAGE;
        const uint32_t sb = sa + 16384;

        #pragma unroll
        for (int kk = 0; kk < 4; kk++){
            const int colb = kk*32 + lh*16;            // byte offset of k within row
            uint32_t af[4][4];
            #pragma unroll
            for (int i = 0; i < 4; i++){
                uint32_t o = (uint32_t)((wm + i*16 + la)*128 + colb);
                ldsm4(af[i][0], af[i][1], af[i][2], af[i][3], sa + SWZ(o));
            }
            uint32_t bfr[2][4];
            #pragma unroll
            for (int j = 0; j < 2; j++){
                uint32_t o = (uint32_t)((wn + j*16 + la)*128 + colb);
                ldsm4(bfr[j][0], bfr[j][1], bfr[j][2], bfr[j][3], sb + SWZ(o));
            }
            #pragma unroll
            for (int i = 0; i < 4; i++)
                #pragma unroll
                for (int jn = 0; jn < 4; jn++){
                    uint32_t b0 = (jn&1) ? bfr[jn>>1][1] : bfr[jn>>1][0];
                    uint32_t b1 = (jn&1) ? bfr[jn>>1][3] : bfr[jn>>1][2];
                    mma16816(acc[i][jn], af[i], b0, b1);
                }
        }
        __syncthreads();
        if (c + 2 < nchunk) LOAD_CHUNK(c + 2, s);
    }
    #undef LOAD_CHUNK

    // ---------------- epilogue (registers -> gmem) ----------------
    const int g  = lane >> 2;
    const int tg = (lane & 3) * 2;

    auto store2 = [&](int row, int cg, float v0, float v1){
        v0 = v0*alpha; v1 = v1*alpha;
        if (bias){ v0 += __ldg(bias+cg); v1 += __ldg(bias+cg+1); }
        if (relu){ v0 = fmaxf(v0,0.f); v1 = fmaxf(v1,0.f); }
        if (mode == 0){
            const ll base = zb*sC1 + zh*sC2 + (ll)row*ldc + cg;
            float2 w = make_float2(v0, v1);
            if (resid){
                float2 rr = *(const float2*)(resid + base);
                w.x += rr.x; w.y += rr.y;
            }
            *(float2*)(Cf + base) = w;
        } else {
            hf h0,l0,h1,l1; trip(v0,h0,l0); trip(v1,h1,l1);
            hf2 hh = __halves2half2(h0,h1);
            hf2 lo = __halves2half2(l0,l1);
            if (mode == 1){
                const ll base = (ll)row*ldc3 + cg;
                *(hf2*)(C2+base)      = hh;
                *(hf2*)(C2+base+toff) = lo;
            } else if (mode == 2 || mode == 3){
                const int b = row>>10, t = row&1023, h = cg>>7, d0 = cg&127;
                const ll base = ((ll)(b*8+h)*1024 + t)*256 + d0;
                *(hf2*)(C2+base) = hh;
                *(hf2*)(C2+base+128) = (mode==2) ? lo : hh;
            } else { // mode 4
                const ll base = ((ll)zb*1024 + row)*2048 + zh*128 + cg;
                *(hf2*)(C2+base)      = hh;
                *(hf2*)(C2+base+1024) = lo;
            }
        }
    };

    #pragma unroll
    for (int i = 0; i < 4; i++){
        const int r0 = blockIdx.y*128 + wm + i*16 + g;
        #pragma unroll
        for (int jn = 0; jn < 4; jn++){
            const int cg = blockIdx.x*128 + wn + jn*8 + tg;
            store2(r0,     cg, acc[i][jn][0], acc[i][jn][1]);
            store2(r0 + 8, cg, acc[i][jn][2], acc[i][jn][3]);
        }
    }
}

// ---------------- fp32 -> fp16 pair ----------------
__global__ void conv_k(const float* __restrict__ in, hf* __restrict__ out,
                       int Kd, int isB, int n)
{
    int i = blockIdx.x*256 + threadIdx.x;
    if (i >= n) return;
    int r = i / Kd, c = i - r*Kd;
    hf h, l; trip(in[i], h, l);
    ll base = (ll)r*2*Kd + c;
    out[base] = h;
    out[base+Kd] = isB ? h : l;
}

// ---------------- LayerNorm -> pair-A, ld 2048 ----------------
__global__ __launch_bounds__(128) void layernorm_k(
    const float* __restrict__ X, hf* __restrict__ Y2,
    const float* __restrict__ g, const float* __restrict__ b)
{
    const int row  = blockIdx.x*4 + (threadIdx.x >> 5);
    const int lane = threadIdx.x & 31;
    const float* p = X + (ll)row*DL;
    float4 v[8]; float s = 0.f;
    #pragma unroll
    for (int i=0;i<8;i++){
        v[i] = *(const float4*)(p + (i*32+lane)*4);
        s += v[i].x + v[i].y + v[i].z + v[i].w;
    }
    #pragma unroll
    for (int o=16;o>0;o>>=1) s += __shfl_xor_sync(0xffffffffu, s, o);
    const float m = s * (1.f/DL);
    float vs = 0.f;
    #pragma unroll
    for (int i=0;i<8;i++){
        float dx=v[i].x-m, dy=v[i].y-m, dz=v[i].z-m, dw=v[i].w-m;
        vs += dx*dx + dy*dy + dz*dz + dw*dw;
    }
    #pragma unroll
    for (int o=16;o>0;o>>=1) vs += __shfl_xor_sync(0xffffffffu, vs, o);
    const float r = rsqrtf(vs*(1.f/DL) + 1e-12f);
    hf* q = Y2 + (ll)row*2048;
    #pragma unroll
    for (int i=0;i<8;i++){
        int c = (i*32+lane)*4;
        float4 gg = *(const float4*)(g + c);
        float4 bb = *(const float4*)(b + c);
        float o0=(v[i].x-m)*r*gg.x+bb.x, o1=(v[i].y-m)*r*gg.y+bb.y;
        float o2=(v[i].z-m)*r*gg.z+bb.z, o3=(v[i].w-m)*r*gg.w+bb.w;
        hf h0,l0,h1,l1,h2,l2,h3,l3;
        trip(o0,h0,l0); trip(o1,h1,l1); trip(o2,h2,l2); trip(o3,h3,l3);
        *(hf2*)(q+c)        = __halves2half2(h0,h1);
        *(hf2*)(q+c+2)      = __halves2half2(h2,h3);
        *(hf2*)(q+1024+c)   = __halves2half2(l0,l1);
        *(hf2*)(q+1024+c+2) = __halves2half2(l2,l3);
    }
}

// ---------------- softmax rows of 1024 -> pair-A, ld 2048 ----------------
__global__ __launch_bounds__(128) void softmax_k(
    const float* __restrict__ S, hf* __restrict__ S2)
{
    const int row  = blockIdx.x*4 + (threadIdx.x >> 5);
    const int lane = threadIdx.x & 31;
    const float* p = S + (ll)row*T_;
    float4 v[8]; float mx = -INFINITY;
    #pragma unroll
    for (int i=0;i<8;i++){
        v[i] = *(const float4*)(p + (i*32+lane)*4);
        mx = fmaxf(mx, fmaxf(fmaxf(v[i].x,v[i].y), fmaxf(v[i].z,v[i].w)));
    }
    #pragma unroll
    for (int o=16;o>0;o>>=1) mx = fmaxf(mx, __shfl_xor_sync(0xffffffffu, mx, o));
    float s = 0.f;
    #pragma unroll
    for (int i=0;i<8;i++){
        v[i].x=__expf(v[i].x-mx); v[i].y=__expf(v[i].y-mx);
        v[i].z=__expf(v[i].z-mx); v[i].w=__expf(v[i].w-mx);
        s += v[i].x + v[i].y + v[i].z + v[i].w;
    }
    #pragma unroll
    for (int o=16;o>0;o>>=1) s += __shfl_xor_sync(0xffffffffu, s, o);
    const float inv = 1.f / s;
    hf* q = S2 + (ll)row*2048;
    #pragma unroll
    for (int i=0;i<8;i++){
        int c = (i*32+lane)*4;
        float o0=v[i].x*inv, o1=v[i].y*inv, o2=v[i].z*inv, o3=v[i].w*inv;
        hf h0,l0,h1,l1,h2,l2,h3,l3;
        trip(o0,h0,l0); trip(o1,h1,l1); trip(o2,h2,l2); trip(o3,h3,l3);
        *(hf2*)(q+c)        = __halves2half2(h0,h1);
        *(hf2*)(q+c+2)      = __halves2half2(h2,h3);
        *(hf2*)(q+1024+c)   = __halves2half2(l0,l1);
        *(hf2*)(q+1024+c+2) = __halves2half2(l2,l3);
    }
}

// ---------------- V transpose -> per-head [d, 2*T] pair-B ----------------
__global__ void vt_k(const float* __restrict__ V, hf* __restrict__ Vt2)
{
    __shared__ float t[32][33];
    const int bh = blockIdx.z, d0 = blockIdx.x*32, t0 = blockIdx.y*32;
    const int b = bh>>3, h = bh&7;
    const int tx = threadIdx.x, ty = threadIdx.y;
    t[ty][tx] = V[((ll)b*T_ + t0+ty)*DL + h*DKH + d0+tx];
    __syncthreads();
    float x = t[tx][ty];
    hf hh = __float2half_rn(x);
    const ll base = ((ll)bh*DKH + d0+ty)*(2*T_) + t0+tx;
    Vt2[base]     = hh;
    Vt2[base+T_]  = hh;
}

// ---------------- host ----------------
static void gm(const hf*A,const hf*B,int M,int N,int Kp,int lda,int ldb,
    ll sA1,ll sA2,ll sB1,ll sB2,int batch,int batch2,int mode,int relu,float alpha,
    const float*bias,const float*resid,float*Cf,ll sC1,ll sC2,int ldc,hf*C2,int toff,int ldc3)
{
    dim3 g(N/128, M/128, batch);
    gemm_m<<<g,256,66560>>>(A,B,Kp,lda,ldb,sA1,sA2,sB1,sB2,batch2,
        mode,relu,alpha,bias,resid,Cf,sC1,sC2,ldc,C2,toff,ldc3);
}
static void conv(const float* in, hf* out, int Kd, int isB, int n){
    conv_k<<<(n+255)/256,256>>>(in, out, Kd, isB, n);
}

extern "C" void kernel_launch(void* const* d_in, const int* in_sizes, int n_in,
                              void* d_out, int out_size)
{
    (void)in_sizes; (void)n_in; (void)out_size;
    const float* x   = (const float*)d_in[0];
    const float* W1  = (const float*)d_in[1];
    const float* b1  = (const float*)d_in[2];
    const float* W2  = (const float*)d_in[3];
    const float* b2  = (const float*)d_in[4];
    const float* ln1g= (const float*)d_in[5];
    const float* ln1b= (const float*)d_in[6];
    const float* ln2g= (const float*)d_in[7];
    const float* ln2b= (const float*)d_in[8];
    const float* Wq  = (const float*)d_in[9];
    const float* bq  = (const float*)d_in[10];
    const float* Wk  = (const float*)d_in[11];
    const float* bk  = (const float*)d_in[12];
    const float* Wv  = (const float*)d_in[13];
    const float* bv  = (const float*)d_in[14];
    const float* Wo  = (const float*)d_in[15];
    const float* bo  = (const float*)d_in[16];
    const float* Fw1 = (const float*)d_in[17];
    const float* Fb1 = (const float*)d_in[18];
    const float* Fw2 = (const float*)d_in[19];
    const float* Fb2 = (const float*)d_in[20];
    float* out = (float*)d_out;

    cudaFuncSetAttribute(gemm_m, cudaFuncAttributeMaxDynamicSharedMemorySize, 66560);

    hf *x2,*W12,*H12,*W22,*Hn2,*Wq2,*Wk2,*Wv2,*Wo2,*Fw12,*Fw22,*Q2,*K2,*Vt2,*S2,*O2,*F12;
    float *X,*V,*S;
    cudaGetSymbolAddress((void**)&x2 , g_x2 );
    cudaGetSymbolAddress((void**)&W12, g_W12);
    cudaGetSymbolAddress((void**)&H12, g_H12);
    cudaGetSymbolAddress((void**)&W22, g_W22);
    cudaGetSymbolAddress((void**)&X  , g_X  );
    cudaGetSymbolAddress((void**)&Hn2, g_Hn2);
    cudaGetSymbolAddress((void**)&Wq2, g_Wq2);
    cudaGetSymbolAddress((void**)&Wk2, g_Wk2);
    cudaGetSymbolAddress((void**)&Wv2, g_Wv2);
    cudaGetSymbolAddress((void**)&Wo2, g_Wo2);
    cudaGetSymbolAddress((void**)&Fw12, g_Fw12);
    cudaGetSymbolAddress((void**)&Fw22, g_Fw22);
    cudaGetSymbolAddress((void**)&Q2 , g_Q2 );
    cudaGetSymbolAddress((void**)&K2 , g_K2 );
    cudaGetSymbolAddress((void**)&V  , g_V  );
    cudaGetSymbolAddress((void**)&Vt2, g_Vt2);
    cudaGetSymbolAddress((void**)&S  , g_S  );
    cudaGetSymbolAddress((void**)&S2 , g_S2 );
    cudaGetSymbolAddress((void**)&O2 , g_O2 );
    cudaGetSymbolAddress((void**)&F12, g_F12);

    const float scl = 0.08838834764831845f; // 128^-0.5

    // ---- downsample ----
    conv(x,  x2,  DL,  0, MROWS*DL);
    conv(W1, W12, DL,  1, DFF*DL);
    conv(W2, W22, DFF, 1, DL*DFF);
    gm(x2, W12, MROWS, DFF, 2*DL, 2*DL, 2*DL, 0,0,0,0, 1,1,
       1,1,1.f, b1, nullptr, nullptr,0,0,0, H12, DFF, 2*DFF);
    gm(H12, W22, MROWS, DL, 2*DFF, 2*DFF, 2*DFF, 0,0,0,0, 1,1,
       0,0,1.f, b2, nullptr, X, 0,0,DL, nullptr,0,0);

    for (int l = 0; l < 2; l++){
        const ll lw = (ll)l*DL*DL;
        conv(Wq+lw, Wq2, DL, 1, DL*DL);
        conv(Wk+lw, Wk2, DL, 1, DL*DL);
        conv(Wv+lw, Wv2, DL, 1, DL*DL);
        conv(Wo+lw, Wo2, DL, 1, DL*DL);
        conv(Fw1+(ll)l*FH*DL, Fw12, DL, 1, FH*DL);
        conv(Fw2+(ll)l*DL*FH, Fw22, FH, 1, DL*FH);

        layernorm_k<<<MROWS/4,128>>>(X, Hn2, ln1g+l*DL, ln1b+l*DL);
        gm(Hn2, Wq2, MROWS, DL, 2*DL, 2*DL, 2*DL, 0,0,0,0, 1,1,
           2,0,1.f, bq+l*DL, nullptr, nullptr,0,0,0, Q2, 0,0);
        gm(Hn2, Wk2, MROWS, DL, 2*DL, 2*DL, 2*DL, 0,0,0,0, 1,1,
           3,0,1.f, bk+l*DL, nullptr, nullptr,0,0,0, K2, 0,0);
        gm(Hn2, Wv2, MROWS, DL, 2*DL, 2*DL, 2*DL, 0,0,0,0, 1,1,
           0,0,1.f, bv+l*DL, nullptr, V, 0,0,DL, nullptr,0,0);
        vt_k<<<dim3(DKH/32, T_/32, B_*NH), dim3(32,32)>>>(V, Vt2);

        // scores = scl * Q @ K^T   [64 batched]
        gm(Q2, K2, T_, T_, 2*DKH, 2*DKH, 2*DKH,
           (ll)NH*T_*2*DKH, (ll)T_*2*DKH, (ll)NH*T_*2*DKH, (ll)T_*2*DKH,
           B_*NH, NH, 0,0,scl, nullptr, nullptr,
           S, (ll)NH*T_*T_, (ll)T_*T_, T_, nullptr,0,0);
        softmax_k<<<(B_*NH*T_)/4,128>>>(S, S2);
        // O = attn @ V   [64 batched]
        gm(S2, Vt2, T_, DKH, 2*T_, 2*T_, 2*T_,
           (ll)NH*T_*2*T_, (ll)T_*2*T_, (ll)NH*DKH*2*T_, (ll)DKH*2*T_,
           B_*NH, NH, 4,0,1.f, nullptr, nullptr,
           nullptr,0,0,0, O2, 0,0);
        // X = X + O @ Wo^T + bo
        gm(O2, Wo2, MROWS, DL, 2*DL, 2*DL, 2*DL, 0,0,0,0, 1,1,
           0,0,1.f, bo+l*DL, X, X, 0,0,DL, nullptr,0,0);

        layernorm_k<<<MROWS/4,128>>>(X, Hn2, ln2g+l*DL, ln2b+l*DL);
        gm(Hn2, Fw12, MROWS, FH, 2*DL, 2*DL, 2*DL, 0,0,0,0, 1,1,
           1,1,1.f, Fb1+l*FH, nullptr, nullptr,0,0,0, F12, FH, 2*FH);
        float* dst = (l==1) ? out : X;
        gm(F12, Fw22, MROWS, DL, 2*FH, 2*FH, 2*FH, 0,0,0,0, 1,1,
           0,0,1.f, Fb2+l*DL, X, dst, 0,0,DL, nullptr,0,0);
    }
}

// round 7
// speedup vs baseline: 3.4206x; 1.0062x over previous
#include <cuda_runtime.h>
#include <cuda_fp16.h>
#include <cstdint>
#include <math.h>
typedef long long ll;
typedef __half hf;
typedef __half2 hf2;

#define B_ 8
#define T_ 1024
#define DL 1024
#define NH 8
#define DKH 128
#define DFF 2048
#define FH 256
#define MROWS 8192

// ---------------- device scratch ----------------
__device__ __align__(128) hf    g_x2 [(size_t)MROWS*2*DL];
__device__ __align__(128) hf    g_W12[(size_t)DFF*2*DL];
__device__ __align__(128) hf    g_H12[(size_t)MROWS*2*DFF];
__device__ __align__(128) hf    g_W22[(size_t)DL*2*DFF];
__device__ __align__(128) float g_X  [(size_t)MROWS*DL];
__device__ __align__(128) hf    g_Hn2[(size_t)MROWS*2*DL];
__device__ __align__(128) hf    g_Wq2[(size_t)DL*2*DL];
__device__ __align__(128) hf    g_Wk2[(size_t)DL*2*DL];
__device__ __align__(128) hf    g_Wv2[(size_t)DL*2*DL];
__device__ __align__(128) hf    g_Wo2[(size_t)DL*2*DL];
__device__ __align__(128) hf    g_Fw12[(size_t)FH*2*DL];
__device__ __align__(128) hf    g_Fw22[(size_t)DL*2*FH];
__device__ __align__(128) hf    g_Q2 [(size_t)MROWS*2*DL];   // (b,h,t) x [hi128|lo128]
__device__ __align__(128) hf    g_K2 [(size_t)MROWS*DL];     // (b,h,t) x hi128
__device__ __align__(128) hf    g_Vh [(size_t)MROWS*DL];     // (b,h,t) x hi128
__device__ __align__(128) hf    g_O2 [(size_t)MROWS*2*DL];
__device__ __align__(128) hf    g_F12[(size_t)MROWS*2*FH];

// ---------------- helpers ----------------
__device__ __forceinline__ uint32_t smem_u32(const void* p){
    uint32_t a;
    asm("{ .reg .u64 t; cvta.to.shared.u64 t, %1; cvt.u32.u64 %0, t; }" : "=r"(a) : "l"(p));
    return a;
}
__device__ __forceinline__ void cp16(uint32_t s, const void* g){
    asm volatile("cp.async.cg.shared.global [%0], [%1], 16;" :: "r"(s), "l"(g));
}
#define CP_COMMIT() asm volatile("cp.async.commit_group;")
#define CP_WAIT0()  asm volatile("cp.async.wait_group 0;" ::: "memory")
#define CP_WAIT1()  asm volatile("cp.async.wait_group 1;" ::: "memory")
#define SWZ(o) ((o) ^ (((o)>>3)&0x70))

__device__ __forceinline__ void ldsm4(uint32_t &r0, uint32_t &r1, uint32_t &r2, uint32_t &r3, uint32_t a){
    asm volatile("ldmatrix.sync.aligned.m8n8.x4.shared.b16 {%0,%1,%2,%3}, [%4];"
                 : "=r"(r0), "=r"(r1), "=r"(r2), "=r"(r3) : "r"(a));
}
__device__ __forceinline__ void ldsm4t(uint32_t &r0, uint32_t &r1, uint32_t &r2, uint32_t &r3, uint32_t a){
    asm volatile("ldmatrix.sync.aligned.m8n8.x4.trans.shared.b16 {%0,%1,%2,%3}, [%4];"
                 : "=r"(r0), "=r"(r1), "=r"(r2), "=r"(r3) : "r"(a));
}
__device__ __forceinline__ void mma16816(float* d, const uint32_t* a, uint32_t b0, uint32_t b1){
    asm volatile("mma.sync.aligned.m16n8k16.row.col.f32.f16.f16.f32 "
                 "{%0,%1,%2,%3}, {%4,%5,%6,%7}, {%8,%9}, {%0,%1,%2,%3};"
                 : "+f"(d[0]), "+f"(d[1]), "+f"(d[2]), "+f"(d[3])
                 : "r"(a[0]), "r"(a[1]), "r"(a[2]), "r"(a[3]), "r"(b0), "r"(b1));
}
__device__ __forceinline__ void trip(float x, hf &h, hf &l){
    h = __float2half_rn(x);
    l = __float2half_rn(x - __half2float(h));
}
__device__ __forceinline__ uint32_t packh(hf a, hf b){
    hf2 t = __halves2half2(a, b);
    return *reinterpret_cast<uint32_t*>(&t);
}

// ================= mma.sync GEMM (dense layers) =================
// modes: 0=fp32 out(+resid), 1=pair-A (ldc3,toff), 2=Q head pair [hi|lo] stride256,
//        3=head single-hi stride128 (K and V)
__global__ __launch_bounds__(256,2) void gemm_m(
    const hf* __restrict__ A, const hf* __restrict__ Bm,
    int Kp, int lda, int ldb,
    ll sA1, ll sA2, ll sB1, ll sB2, int batch2,
    int mode, int relu, float alpha,
    const float* __restrict__ bias, const float* __restrict__ resid,
    float* __restrict__ Cf, ll sC1, ll sC2, int ldc,
    hf* __restrict__ C2, int toff, int ldc3)
{
    constexpr int STAGE = 32768;
    extern __shared__ char dyn[];
    const uint32_t sbase = (smem_u32(dyn) + 1023) & ~1023u;

    const int tid  = threadIdx.x;
    const int lane = tid & 31;
    const int wid  = tid >> 5;
    const int wm   = (wid >> 2) * 64;
    const int wn   = (wid & 3) * 32;

    const int z  = blockIdx.z;
    const int zb = z / batch2, zh = z - zb*batch2;
    const hf* Ab = A  + zb*sA1 + zh*sA2 + (ll)blockIdx.y*128*lda;
    const hf* Bb = Bm + zb*sB1 + zh*sB2 + (ll)blockIdx.x*128*ldb;

    float acc[4][4][4];
    #pragma unroll
    for (int i=0;i<4;i++)
        #pragma unroll
        for (int j=0;j<4;j++)
            #pragma unroll
            for (int r=0;r<4;r++) acc[i][j][r] = 0.f;

    const int nchunk = Kp >> 6;

    #define LOAD_CHUNK(c, s) do { \
        const int k0_ = (c) << 6; \
        const uint32_t sa_ = sbase + (s)*STAGE; \
        const uint32_t sb_ = sa_ + 16384; \
        _Pragma("unroll") \
        for (int i_ = 0; i_ < 4; i_++){ \
            int idx_ = tid + i_*256; \
            int r_ = idx_>>3, j_ = idx_&7; \
            cp16(sa_ + SWZ(r_*128 + j_*16), Ab + (ll)r_*lda + k0_ + j_*8); \
        } \
        _Pragma("unroll") \
        for (int i_ = 0; i_ < 4; i_++){ \
            int idx_ = tid + i_*256; \
            int r_ = idx_>>3, j_ = idx_&7; \
            cp16(sb_ + SWZ(r_*128 + j_*16), Bb + (ll)r_*ldb + k0_ + j_*8); \
        } \
        CP_COMMIT(); \
    } while(0)

    LOAD_CHUNK(0, 0);
    if (nchunk > 1) LOAD_CHUNK(1, 1);

    const int la = lane & 15;
    const int lh = lane >> 4;

    for (int c = 0; c < nchunk; c++){
        if (c + 1 < nchunk) { CP_WAIT1(); } else { CP_WAIT0(); }
        __syncthreads();
        const int s = c & 1;
        const uint32_t sa = sbase + s*STAGE;
        const uint32_t sb = sa + 16384;

        #pragma unroll
        for (int kk = 0; kk < 4; kk++){
            const int colb = kk*32 + lh*16;
            uint32_t af[4][4];
            #pragma unroll
            for (int i = 0; i < 4; i++){
                uint32_t o = (uint32_t)((wm + i*16 + la)*128 + colb);
                ldsm4(af[i][0], af[i][1], af[i][2], af[i][3], sa + SWZ(o));
            }
            uint32_t bfr[2][4];
            #pragma unroll
            for (int j = 0; j < 2; j++){
                uint32_t o = (uint32_t)((wn + j*16 + la)*128 + colb);
                ldsm4(bfr[j][0], bfr[j][1], bfr[j][2], bfr[j][3], sb + SWZ(o));
            }
            #pragma unroll
            for (int i = 0; i < 4; i++)
                #pragma unroll
                for (int jn = 0; jn < 4; jn++){
                    uint32_t b0 = (jn&1) ? bfr[jn>>1][1] : bfr[jn>>1][0];
                    uint32_t b1 = (jn&1) ? bfr[jn>>1][3] : bfr[jn>>1][2];
                    mma16816(acc[i][jn], af[i], b0, b1);
                }
        }
        __syncthreads();
        if (c + 2 < nchunk) LOAD_CHUNK(c + 2, s);
    }
    #undef LOAD_CHUNK

    const int g  = lane >> 2;
    const int tg = (lane & 3) * 2;

    auto store2 = [&](int row, int cg, float v0, float v1){
        if (bias){ v0 += __ldg(bias+cg); v1 += __ldg(bias+cg+1); }
        v0 *= alpha; v1 *= alpha;
        if (relu){ v0 = fmaxf(v0,0.f); v1 = fmaxf(v1,0.f); }
        if (mode == 0){
            const ll base = zb*sC1 + zh*sC2 + (ll)row*ldc + cg;
            float2 w = make_float2(v0, v1);
            if (resid){
                float2 rr = *(const float2*)(resid + base);
                w.x += rr.x; w.y += rr.y;
            }
            *(float2*)(Cf + base) = w;
        } else if (mode == 1){
            hf h0,l0,h1,l1; trip(v0,h0,l0); trip(v1,h1,l1);
            const ll base = (ll)row*ldc3 + cg;
            *(hf2*)(C2+base)      = __halves2half2(h0,h1);
            *(hf2*)(C2+base+toff) = __halves2half2(l0,l1);
        } else if (mode == 2){
            hf h0,l0,h1,l1; trip(v0,h0,l0); trip(v1,h1,l1);
            const int b = row>>10, t = row&1023, h = cg>>7, d0 = cg&127;
            const ll base = ((ll)(b*8+h)*1024 + t)*256 + d0;
            *(hf2*)(C2+base)     = __halves2half2(h0,h1);
            *(hf2*)(C2+base+128) = __halves2half2(l0,l1);
        } else { // mode 3: single hi, stride 128
            const int b = row>>10, t = row&1023, h = cg>>7, d0 = cg&127;
            const ll base = ((ll)(b*8+h)*1024 + t)*128 + d0;
            *(hf2*)(C2+base) = __halves2half2(__float2half_rn(v0), __float2half_rn(v1));
        }
    };

    #pragma unroll
    for (int i = 0; i < 4; i++){
        const int r0 = blockIdx.y*128 + wm + i*16 + g;
        #pragma unroll
        for (int jn = 0; jn < 4; jn++){
            const int cg = blockIdx.x*128 + wn + jn*8 + tg;
            store2(r0,     cg, acc[i][jn][0], acc[i][jn][1]);
            store2(r0 + 8, cg, acc[i][jn][2], acc[i][jn][3]);
        }
    }
}

// ================= flash attention =================
// grid (8 qtiles, 64 bh), 256 threads = 8 warps; warp w owns rows 16w..16w+15.
// Q pair [hi|lo] (scl pre-folded), K/V single-hi. O written pair to O2 layout.
// smem: sQ 4x16KB | sK 2buf x 2x16KB | sV 2buf x 2x16KB = 192KB
__global__ __launch_bounds__(256,1) void flash_k(
    const hf* __restrict__ Q2, const hf* __restrict__ K2,
    const hf* __restrict__ Vh, hf* __restrict__ O2)
{
    extern __shared__ char dyn[];
    const uint32_t sb = (smem_u32(dyn) + 1023) & ~1023u;
    const int tid = threadIdx.x, lane = tid & 31, wid = tid >> 5;
    const int qt = blockIdx.x, bh = blockIdx.y;
    const int b = bh >> 3, h = bh & 7;
    const int la = lane & 15, lh = lane >> 4;
    const int g = lane >> 2, tg = (lane & 3) * 2;

    const hf* Qg = Q2 + ((ll)bh*1024 + qt*128)*256;
    const hf* Kg = K2 + ((ll)bh*1024)*128;
    const hf* Vg = Vh + ((ll)bh*1024)*128;

    #define LCH(sb_, gp_, ld_) do{ _Pragma("unroll") \
        for (int i_=0;i_<4;i_++){ int idx_=tid+i_*256; int r_=idx_>>3, j_=idx_&7; \
            cp16((sb_)+SWZ(r_*128+j_*16), (gp_)+(ll)r_*(ld_)+j_*8); } }while(0)

    // initial loads: Q (4 chunks) + KV tile0  | group A ; KV tile1 | group B
    #pragma unroll
    for (int c=0;c<4;c++) LCH(sb + c*16384, Qg + c*64, 256);
    #pragma unroll
    for (int c=0;c<2;c++) LCH(sb + 65536 + c*16384, Kg + c*64, 128);
    #pragma unroll
    for (int c=0;c<2;c++) LCH(sb + 131072 + c*16384, Vg + c*64, 128);
    CP_COMMIT();
    #pragma unroll
    for (int c=0;c<2;c++) LCH(sb + 65536+32768 + c*16384, Kg + (ll)128*128 + c*64, 128);
    #pragma unroll
    for (int c=0;c<2;c++) LCH(sb + 131072+32768 + c*16384, Vg + (ll)128*128 + c*64, 128);
    CP_COMMIT();

    float oacc[8][2][4];
    #pragma unroll
    for (int j=0;j<8;j++)
        #pragma unroll
        for (int hh=0;hh<2;hh++)
            #pragma unroll
            for (int r=0;r<4;r++) oacc[j][hh][r] = 0.f;
    float mrow[2] = {-INFINITY, -INFINITY};
    float lrow[2] = {0.f, 0.f};

    for (int kt = 0; kt < 8; kt++){
        if (kt + 1 < 8) { CP_WAIT1(); } else { CP_WAIT0(); }
        __syncthreads();
        const int s = kt & 1;
        const uint32_t kbase = sb + 65536 + s*32768;
        const uint32_t vbase = sb + 131072 + s*32768;

        // ---- S = Q(hi+lo) @ K_hi^T ----
        float sacc[8][2][4];
        #pragma unroll
        for (int nb=0;nb<8;nb++)
            #pragma unroll
            for (int hh=0;hh<2;hh++)
                #pragma unroll
                for (int r=0;r<4;r++) sacc[nb][hh][r] = 0.f;

        #pragma unroll
        for (int pass = 0; pass < 2; pass++){
            #pragma unroll
            for (int ks = 0; ks < 8; ks++){
                const int colb = (ks&3)*32 + lh*16;
                uint32_t a[4];
                ldsm4(a[0],a[1],a[2],a[3],
                      sb + (pass*2 + (ks>>2))*16384 + SWZ((wid*16+la)*128 + colb));
                #pragma unroll
                for (int nb = 0; nb < 8; nb++){
                    uint32_t r0,r1,r2,r3;
                    ldsm4(r0,r1,r2,r3,
                          kbase + (ks>>2)*16384 + SWZ((nb*16+la)*128 + colb));
                    mma16816(sacc[nb][0], a, r0, r2);
                    mma16816(sacc[nb][1], a, r1, r3);
                }
            }
        }

        // ---- online softmax (rows g, g+8 per thread; quad = 4 lanes per row) ----
        float pscale[2];
        #pragma unroll
        for (int r = 0; r < 2; r++){
            float mx = -INFINITY;
            #pragma unroll
            for (int nb=0;nb<8;nb++)
                #pragma unroll
                for (int hh=0;hh<2;hh++)
                    mx = fmaxf(mx, fmaxf(sacc[nb][hh][r*2], sacc[nb][hh][r*2+1]));
            mx = fmaxf(mx, __shfl_xor_sync(0xffffffffu, mx, 1));
            mx = fmaxf(mx, __shfl_xor_sync(0xffffffffu, mx, 2));
            const float mnew = fmaxf(mrow[r], mx);
            pscale[r] = __expf(mrow[r] - mnew);
            float ls = 0.f;
            #pragma unroll
            for (int nb=0;nb<8;nb++)
                #pragma unroll
                for (int hh=0;hh<2;hh++){
                    float p0 = __expf(sacc[nb][hh][r*2]   - mnew);
                    float p1 = __expf(sacc[nb][hh][r*2+1] - mnew);
                    sacc[nb][hh][r*2] = p0; sacc[nb][hh][r*2+1] = p1;
                    ls += p0 + p1;
                }
            ls += __shfl_xor_sync(0xffffffffu, ls, 1);
            ls += __shfl_xor_sync(0xffffffffu, ls, 2);
            lrow[r] = lrow[r]*pscale[r] + ls;
            mrow[r] = mnew;
        }
        #pragma unroll
        for (int j=0;j<8;j++)
            #pragma unroll
            for (int hh=0;hh<2;hh++){
                oacc[j][hh][0] *= pscale[0]; oacc[j][hh][1] *= pscale[0];
                oacc[j][hh][2] *= pscale[1]; oacc[j][hh][3] *= pscale[1];
            }

        // ---- O += P(hi+lo) @ V_hi ----
        #pragma unroll
        for (int nb = 0; nb < 8; nb++){
            uint32_t ahi[4], alo[4];
            {
                float p[8] = { sacc[nb][0][0], sacc[nb][0][1], sacc[nb][0][2], sacc[nb][0][3],
                               sacc[nb][1][0], sacc[nb][1][1], sacc[nb][1][2], sacc[nb][1][3] };
                hf ph[8]; float pl[8];
                #pragma unroll
                for (int q=0;q<8;q++){ ph[q]=__float2half_rn(p[q]); pl[q]=p[q]-__half2float(ph[q]); }
                ahi[0]=packh(ph[0],ph[1]); ahi[1]=packh(ph[2],ph[3]);
                ahi[2]=packh(ph[4],ph[5]); ahi[3]=packh(ph[6],ph[7]);
                alo[0]=packh(__float2half_rn(pl[0]),__float2half_rn(pl[1]));
                alo[1]=packh(__float2half_rn(pl[2]),__float2half_rn(pl[3]));
                alo[2]=packh(__float2half_rn(pl[4]),__float2half_rn(pl[5]));
                alo[3]=packh(__float2half_rn(pl[6]),__float2half_rn(pl[7]));
            }
            #pragma unroll
            for (int j = 0; j < 8; j++){
                uint32_t r0,r1,r2,r3;
                ldsm4t(r0,r1,r2,r3,
                       vbase + (j>>2)*16384 + SWZ((nb*16+la)*128 + (j&3)*32 + lh*16));
                mma16816(oacc[j][0], ahi, r0, r1);
                mma16816(oacc[j][1], ahi, r2, r3);
                mma16816(oacc[j][0], alo, r0, r1);
                mma16816(oacc[j][1], alo, r2, r3);
            }
        }
        __syncthreads();
        if (kt + 2 < 8){
            #pragma unroll
            for (int c=0;c<2;c++) LCH(sb + 65536  + s*32768 + c*16384, Kg + (ll)(kt+2)*128*128 + c*64, 128);
            #pragma unroll
            for (int c=0;c<2;c++) LCH(sb + 131072 + s*32768 + c*16384, Vg + (ll)(kt+2)*128*128 + c*64, 128);
            CP_COMMIT();
        }
    }
    #undef LCH

    // ---- epilogue: O/l -> pair to O2 ----
    #pragma unroll
    for (int r = 0; r < 2; r++){
        const int t = qt*128 + wid*16 + g + r*8;
        const float inv = 1.f / lrow[r];
        const ll base0 = ((ll)(b*1024 + t))*2048 + h*128;
        #pragma unroll
        for (int j = 0; j < 8; j++)
            #pragma unroll
            for (int hh = 0; hh < 2; hh++){
                const int d = j*16 + hh*8 + tg;
                float v0 = oacc[j][hh][r*2]   * inv;
                float v1 = oacc[j][hh][r*2+1] * inv;
                hf h0,l0,h1,l1; trip(v0,h0,l0); trip(v1,h1,l1);
                *(hf2*)(O2 + base0 + d)        = __halves2half2(h0,h1);
                *(hf2*)(O2 + base0 + 1024 + d) = __halves2half2(l0,l1);
            }
    }
}

// ---------------- fp32 -> fp16 pair ----------------
__global__ void conv_k(const float* __restrict__ in, hf* __restrict__ out,
                       int Kd, int isB, int n)
{
    int i = blockIdx.x*256 + threadIdx.x;
    if (i >= n) return;
    int r = i / Kd, c = i - r*Kd;
    hf h, l; trip(in[i], h, l);
    ll base = (ll)r*2*Kd + c;
    out[base] = h;
    out[base+Kd] = isB ? h : l;
}

// ---------------- LayerNorm -> pair-A, ld 2048 ----------------
__global__ __launch_bounds__(128) void layernorm_k(
    const float* __restrict__ X, hf* __restrict__ Y2,
    const float* __restrict__ g, const float* __restrict__ b)
{
    const int row  = blockIdx.x*4 + (threadIdx.x >> 5);
    const int lane = threadIdx.x & 31;
    const float* p = X + (ll)row*DL;
    float4 v[8]; float s = 0.f;
    #pragma unroll
    for (int i=0;i<8;i++){
        v[i] = *(const float4*)(p + (i*32+lane)*4);
        s += v[i].x + v[i].y + v[i].z + v[i].w;
    }
    #pragma unroll
    for (int o=16;o>0;o>>=1) s += __shfl_xor_sync(0xffffffffu, s, o);
    const float m = s * (1.f/DL);
    float vs = 0.f;
    #pragma unroll
    for (int i=0;i<8;i++){
        float dx=v[i].x-m, dy=v[i].y-m, dz=v[i].z-m, dw=v[i].w-m;
        vs += dx*dx + dy*dy + dz*dz + dw*dw;
    }
    #pragma unroll
    for (int o=16;o>0;o>>=1) vs += __shfl_xor_sync(0xffffffffu, vs, o);
    const float r = rsqrtf(vs*(1.f/DL) + 1e-12f);
    hf* q = Y2 + (ll)row*2048;
    #pragma unroll
    for (int i=0;i<8;i++){
        int c = (i*32+lane)*4;
        float4 gg = *(const float4*)(g + c);
        float4 bb = *(const float4*)(b + c);
        float o0=(v[i].x-m)*r*gg.x+bb.x, o1=(v[i].y-m)*r*gg.y+bb.y;
        float o2=(v[i].z-m)*r*gg.z+bb.z, o3=(v[i].w-m)*r*gg.w+bb.w;
        hf h0,l0,h1,l1,h2,l2,h3,l3;
        trip(o0,h0,l0); trip(o1,h1,l1); trip(o2,h2,l2); trip(o3,h3,l3);
        *(hf2*)(q+c)        = __halves2half2(h0,h1);
        *(hf2*)(q+c+2)      = __halves2half2(h2,h3);
        *(hf2*)(q+1024+c)   = __halves2half2(l0,l1);
        *(hf2*)(q+1024+c+2) = __halves2half2(l2,l3);
    }
}

// ---------------- host ----------------
static void gm(const hf*A,const hf*B,int M,int N,int Kp,int lda,int ldb,
    ll sA1,ll sA2,ll sB1,ll sB2,int batch,int batch2,int mode,int relu,float alpha,
    const float*bias,const float*resid,float*Cf,ll sC1,ll sC2,int ldc,hf*C2,int toff,int ldc3)
{
    dim3 g(N/128, M/128, batch);
    gemm_m<<<g,256,66560>>>(A,B,Kp,lda,ldb,sA1,sA2,sB1,sB2,batch2,
        mode,relu,alpha,bias,resid,Cf,sC1,sC2,ldc,C2,toff,ldc3);
}
static void conv(const float* in, hf* out, int Kd, int isB, int n){
    conv_k<<<(n+255)/256,256>>>(in, out, Kd, isB, n);
}

extern "C" void kernel_launch(void* const* d_in, const int* in_sizes, int n_in,
                              void* d_out, int out_size)
{
    (void)in_sizes; (void)n_in; (void)out_size;
    const float* x   = (const float*)d_in[0];
    const float* W1  = (const float*)d_in[1];
    const float* b1  = (const float*)d_in[2];
    const float* W2  = (const float*)d_in[3];
    const float* b2  = (const float*)d_in[4];
    const float* ln1g= (const float*)d_in[5];
    const float* ln1b= (const float*)d_in[6];
    const float* ln2g= (const float*)d_in[7];
    const float* ln2b= (const float*)d_in[8];
    const float* Wq  = (const float*)d_in[9];
    const float* bq  = (const float*)d_in[10];
    const float* Wk  = (const float*)d_in[11];
    const float* bk  = (const float*)d_in[12];
    const float* Wv  = (const float*)d_in[13];
    const float* bv  = (const float*)d_in[14];
    const float* Wo  = (const float*)d_in[15];
    const float* bo  = (const float*)d_in[16];
    const float* Fw1 = (const float*)d_in[17];
    const float* Fb1 = (const float*)d_in[18];
    const float* Fw2 = (const float*)d_in[19];
    const float* Fb2 = (const float*)d_in[20];
    float* out = (float*)d_out;

    cudaFuncSetAttribute(gemm_m, cudaFuncAttributeMaxDynamicSharedMemorySize, 66560);
    cudaFuncSetAttribute(flash_k, cudaFuncAttributeMaxDynamicSharedMemorySize, 197632);

    hf *x2,*W12,*H12,*W22,*Hn2,*Wq2,*Wk2,*Wv2,*Wo2,*Fw12,*Fw22,*Q2,*K2,*Vh,*O2,*F12;
    float *X;
    cudaGetSymbolAddress((void**)&x2 , g_x2 );
    cudaGetSymbolAddress((void**)&W12, g_W12);
    cudaGetSymbolAddress((void**)&H12, g_H12);
    cudaGetSymbolAddress((void**)&W22, g_W22);
    cudaGetSymbolAddress((void**)&X  , g_X  );
    cudaGetSymbolAddress((void**)&Hn2, g_Hn2);
    cudaGetSymbolAddress((void**)&Wq2, g_Wq2);
    cudaGetSymbolAddress((void**)&Wk2, g_Wk2);
    cudaGetSymbolAddress((void**)&Wv2, g_Wv2);
    cudaGetSymbolAddress((void**)&Wo2, g_Wo2);
    cudaGetSymbolAddress((void**)&Fw12, g_Fw12);
    cudaGetSymbolAddress((void**)&Fw22, g_Fw22);
    cudaGetSymbolAddress((void**)&Q2 , g_Q2 );
    cudaGetSymbolAddress((void**)&K2 , g_K2 );
    cudaGetSymbolAddress((void**)&Vh , g_Vh );
    cudaGetSymbolAddress((void**)&O2 , g_O2 );
    cudaGetSymbolAddress((void**)&F12, g_F12);

    const float scl = 0.08838834764831845f; // 128^-0.5

    // ---- downsample ----
    conv(x,  x2,  DL,  0, MROWS*DL);
    conv(W1, W12, DL,  1, DFF*DL);
    conv(W2, W22, DFF, 1, DL*DFF);
    gm(x2, W12, MROWS, DFF, 2*DL, 2*DL, 2*DL, 0,0,0,0, 1,1,
       1,1,1.f, b1, nullptr, nullptr,0,0,0, H12, DFF, 2*DFF);
    gm(H12, W22, MROWS, DL, 2*DFF, 2*DFF, 2*DFF, 0,0,0,0, 1,1,
       0,0,1.f, b2, nullptr, X, 0,0,DL, nullptr,0,0);

    for (int l = 0; l < 2; l++){
        const ll lw = (ll)l*DL*DL;
        conv(Wq+lw, Wq2, DL, 1, DL*DL);
        conv(Wk+lw, Wk2, DL, 1, DL*DL);
        conv(Wv+lw, Wv2, DL, 1, DL*DL);
        conv(Wo+lw, Wo2, DL, 1, DL*DL);
        conv(Fw1+(ll)l*FH*DL, Fw12, DL, 1, FH*DL);
        conv(Fw2+(ll)l*DL*FH, Fw22, FH, 1, DL*FH);

        layernorm_k<<<MROWS/4,128>>>(X, Hn2, ln1g+l*DL, ln1b+l*DL);
        // Q: pair layout, scl folded via alpha (bias applied before alpha)
        gm(Hn2, Wq2, MROWS, DL, 2*DL, 2*DL, 2*DL, 0,0,0,0, 1,1,
           2,0,scl, bq+l*DL, nullptr, nullptr,0,0,0, Q2, 0,0);
        // K, V: single-hi per-head layout
        gm(Hn2, Wk2, MROWS, DL, 2*DL, 2*DL, 2*DL, 0,0,0,0, 1,1,
           3,0,1.f, bk+l*DL, nullptr, nullptr,0,0,0, K2, 0,0);
        gm(Hn2, Wv2, MROWS, DL, 2*DL, 2*DL, 2*DL, 0,0,0,0, 1,1,
           3,0,1.f, bv+l*DL, nullptr, nullptr,0,0,0, Vh, 0,0);

        flash_k<<<dim3(8,64),256,197632>>>(Q2, K2, Vh, O2);

        // X = X + O @ Wo^T + bo
        gm(O2, Wo2, MROWS, DL, 2*DL, 2*DL, 2*DL, 0,0,0,0, 1,1,
           0,0,1.f, bo+l*DL, X, X, 0,0,DL, nullptr,0,0);

        layernorm_k<<<MROWS/4,128>>>(X, Hn2, ln2g+l*DL, ln2b+l*DL);
        gm(Hn2, Fw12, MROWS, FH, 2*DL, 2*DL, 2*DL, 0,0,0,0, 1,1,
           1,1,1.f, Fb1+l*FH, nullptr, nullptr,0,0,0, F12, FH, 2*FH);
        float* dst = (l==1) ? out : X;
        gm(F12, Fw22, MROWS, DL, 2*FH, 2*FH, 2*FH, 0,0,0,0, 1,1,
           0,0,1.f, Fb2+l*DL, X, dst, 0,0,DL, nullptr,0,0);
    }
}